// round 1
// baseline (speedup 1.0000x reference)
#include <cuda_runtime.h>
#include <math.h>

#define T 2048
#define H 1024
#define M 512
#define E 32
#define TOPK 4

// ---------------- device scratch (static: no allocations allowed) ----------
__device__ int   g_count[E];            // tokens routed to each expert
__device__ int   g_tok[E * T];          // packed assignment id: token*4 + k
__device__ float g_wt[E * T];           // softmax routing weight
__device__ float g_h[T * TOPK * M];     // mixed = silu(gate)*up*route, per assignment (16 MB)

// ---------------- zero counters + output ----------------------------------
__global__ void zero_kernel(float* __restrict__ out) {
    int i = blockIdx.x * blockDim.x + threadIdx.x;
    if (i < E) g_count[i] = 0;
    int stride = gridDim.x * blockDim.x;
    for (int j = i; j < T * H; j += stride) out[j] = 0.0f;
}

// ---------------- router: logits -> top4 -> softmax -> expert lists --------
__global__ void router_kernel(const float* __restrict__ x,
                              const float* __restrict__ gate_w) {
    __shared__ float xs[H];
    __shared__ float logits[E];
    int t = blockIdx.x;
    const float* xr = x + (size_t)t * H;
    for (int i = threadIdx.x; i < H; i += blockDim.x) xs[i] = xr[i];
    __syncthreads();
    int warp = threadIdx.x >> 5, lane = threadIdx.x & 31;
    for (int e = warp; e < E; e += 4) {
        const float* w = gate_w + (size_t)e * H;
        float s = 0.f;
        for (int i = lane; i < H; i += 32) s += xs[i] * w[i];
        #pragma unroll
        for (int o = 16; o > 0; o >>= 1) s += __shfl_xor_sync(0xffffffffu, s, o);
        if (lane == 0) logits[e] = s;
    }
    __syncthreads();
    if (threadIdx.x == 0) {
        int ids[TOPK]; float vals[TOPK];
        unsigned used = 0;
        for (int k = 0; k < TOPK; k++) {
            float best = -INFINITY; int bi = 0;
            for (int e = 0; e < E; e++) {
                if (!((used >> e) & 1u) && logits[e] > best) { best = logits[e]; bi = e; }
            }
            used |= (1u << bi); ids[k] = bi; vals[k] = best;
        }
        float mx = vals[0], se = 0.f, w4[TOPK];
        for (int k = 0; k < TOPK; k++) { w4[k] = expf(vals[k] - mx); se += w4[k]; }
        float inv = 1.0f / se;
        for (int k = 0; k < TOPK; k++) {
            int e = ids[k];
            int pos = atomicAdd(&g_count[e], 1);
            g_tok[e * T + pos] = t * TOPK + k;
            g_wt[e * T + pos] = w4[k] * inv;
        }
    }
}

// ---------------- gate/up GEMM: 64 tokens x 128 m cols per block -----------
// gate[t,m] = x[t,:] . w_gate[e,m,:]; up likewise; h = silu(gate)*up*route_w
__global__ __launch_bounds__(256, 2)
void gateup_kernel(const float* __restrict__ x,
                   const float* __restrict__ wg,
                   const float* __restrict__ wu) {
    int e = blockIdx.z;
    int n = g_count[e];
    int t0 = blockIdx.y * 64;
    if (t0 >= n) return;
    int m0 = blockIdx.x * 128;

    __shared__ float Xs[32][68];    // [k][token] transposed, padded
    __shared__ float Gs[32][132];   // [k][m]
    __shared__ float Us[32][132];
    __shared__ int   stok[64];
    __shared__ int   said[64];
    __shared__ float swt[64];

    int tid = threadIdx.x;
    if (tid < 64) {
        int slot = t0 + tid;
        if (slot < n) {
            int v = g_tok[e * T + slot];
            stok[tid] = v >> 2;
            said[tid] = v;
            swt[tid]  = g_wt[e * T + slot];
        } else { stok[tid] = -1; said[tid] = -1; swt[tid] = 0.f; }
    }
    __syncthreads();

    float accg[8][4], accu[8][4];
    #pragma unroll
    for (int i = 0; i < 8; i++)
        #pragma unroll
        for (int j = 0; j < 4; j++) { accg[i][j] = 0.f; accu[i][j] = 0.f; }

    int tx = tid & 31;          // m group (4 cols)
    int ty = tid >> 5;          // token group (8 rows)
    int lrow = tid >> 3;        // loader row 0..31
    int kb = (tid & 7) << 2;    // loader k base (float4)
    const float* wgb = wg + ((size_t)e * M + m0) * H;
    const float* wub = wu + ((size_t)e * M + m0) * H;

    for (int k0 = 0; k0 < H; k0 += 32) {
        #pragma unroll
        for (int p = 0; p < 2; p++) {
            int r = lrow + p * 32;
            int tok = stok[r];
            float4 v = make_float4(0.f, 0.f, 0.f, 0.f);
            if (tok >= 0) v = *(const float4*)(x + (size_t)tok * H + k0 + kb);
            Xs[kb+0][r] = v.x; Xs[kb+1][r] = v.y; Xs[kb+2][r] = v.z; Xs[kb+3][r] = v.w;
        }
        #pragma unroll
        for (int p = 0; p < 4; p++) {
            int r = lrow + p * 32;
            float4 g4 = *(const float4*)(wgb + (size_t)r * H + k0 + kb);
            Gs[kb+0][r] = g4.x; Gs[kb+1][r] = g4.y; Gs[kb+2][r] = g4.z; Gs[kb+3][r] = g4.w;
            float4 u4 = *(const float4*)(wub + (size_t)r * H + k0 + kb);
            Us[kb+0][r] = u4.x; Us[kb+1][r] = u4.y; Us[kb+2][r] = u4.z; Us[kb+3][r] = u4.w;
        }
        __syncthreads();
        #pragma unroll
        for (int kk = 0; kk < 32; kk++) {
            float4 a0 = *(const float4*)&Xs[kk][ty * 8];
            float4 a1 = *(const float4*)&Xs[kk][ty * 8 + 4];
            float4 g4 = *(const float4*)&Gs[kk][tx * 4];
            float4 u4 = *(const float4*)&Us[kk][tx * 4];
            float a[8]  = {a0.x, a0.y, a0.z, a0.w, a1.x, a1.y, a1.z, a1.w};
            float gg[4] = {g4.x, g4.y, g4.z, g4.w};
            float uu[4] = {u4.x, u4.y, u4.z, u4.w};
            #pragma unroll
            for (int i = 0; i < 8; i++)
                #pragma unroll
                for (int j = 0; j < 4; j++) {
                    accg[i][j] += a[i] * gg[j];
                    accu[i][j] += a[i] * uu[j];
                }
        }
        __syncthreads();
    }

    #pragma unroll
    for (int i = 0; i < 8; i++) {
        int r = ty * 8 + i;
        int aid = said[r];
        if (aid < 0) continue;
        float w = swt[r];
        float tmp[4];
        #pragma unroll
        for (int j = 0; j < 4; j++) {
            float g = accg[i][j];
            float s = g / (1.0f + expf(-g));
            tmp[j] = s * accu[i][j] * w;
        }
        float4 hv; hv.x = tmp[0]; hv.y = tmp[1]; hv.z = tmp[2]; hv.w = tmp[3];
        *(float4*)(g_h + (size_t)aid * M + m0 + tx * 4) = hv;
    }
}

// ---------------- down GEMM: out[t,h] += h[a,:] . w_down[e,h,:] ------------
__global__ __launch_bounds__(256, 2)
void down_kernel(const float* __restrict__ wd, float* __restrict__ out) {
    int e = blockIdx.z;
    int n = g_count[e];
    int t0 = blockIdx.y * 64;
    if (t0 >= n) return;
    int h0 = blockIdx.x * 128;

    __shared__ float As[32][68];    // [k=m][token]
    __shared__ float Ws[32][132];   // [k=m][h]
    __shared__ int   said[64];

    int tid = threadIdx.x;
    if (tid < 64) {
        int slot = t0 + tid;
        said[tid] = (slot < n) ? g_tok[e * T + slot] : -1;
    }
    __syncthreads();

    float acc[8][4];
    #pragma unroll
    for (int i = 0; i < 8; i++)
        #pragma unroll
        for (int j = 0; j < 4; j++) acc[i][j] = 0.f;

    int tx = tid & 31;
    int ty = tid >> 5;
    int lrow = tid >> 3;
    int kb = (tid & 7) << 2;
    const float* wdb = wd + ((size_t)e * H + h0) * M;

    for (int k0 = 0; k0 < M; k0 += 32) {
        #pragma unroll
        for (int p = 0; p < 2; p++) {
            int r = lrow + p * 32;
            int aid = said[r];
            float4 v = make_float4(0.f, 0.f, 0.f, 0.f);
            if (aid >= 0) v = *(const float4*)(g_h + (size_t)aid * M + k0 + kb);
            As[kb+0][r] = v.x; As[kb+1][r] = v.y; As[kb+2][r] = v.z; As[kb+3][r] = v.w;
        }
        #pragma unroll
        for (int p = 0; p < 4; p++) {
            int r = lrow + p * 32;
            float4 w4 = *(const float4*)(wdb + (size_t)r * M + k0 + kb);
            Ws[kb+0][r] = w4.x; Ws[kb+1][r] = w4.y; Ws[kb+2][r] = w4.z; Ws[kb+3][r] = w4.w;
        }
        __syncthreads();
        #pragma unroll
        for (int kk = 0; kk < 32; kk++) {
            float4 a0 = *(const float4*)&As[kk][ty * 8];
            float4 a1 = *(const float4*)&As[kk][ty * 8 + 4];
            float4 w4 = *(const float4*)&Ws[kk][tx * 4];
            float a[8]  = {a0.x, a0.y, a0.z, a0.w, a1.x, a1.y, a1.z, a1.w};
            float ww[4] = {w4.x, w4.y, w4.z, w4.w};
            #pragma unroll
            for (int i = 0; i < 8; i++)
                #pragma unroll
                for (int j = 0; j < 4; j++)
                    acc[i][j] += a[i] * ww[j];
        }
        __syncthreads();
    }

    #pragma unroll
    for (int i = 0; i < 8; i++) {
        int aid = said[ty * 8 + i];
        if (aid < 0) continue;
        int t = aid >> 2;
        float* op = out + (size_t)t * H + h0 + tx * 4;
        #pragma unroll
        for (int j = 0; j < 4; j++) atomicAdd(op + j, acc[i][j]);
    }
}

// ---------------- launcher -------------------------------------------------
extern "C" void kernel_launch(void* const* d_in, const int* in_sizes, int n_in,
                              void* d_out, int out_size) {
    const float* x      = (const float*)d_in[0];
    const float* gate_w = (const float*)d_in[1];
    const float* w_gate = (const float*)d_in[2];
    const float* w_up   = (const float*)d_in[3];
    const float* w_down = (const float*)d_in[4];
    float* out = (float*)d_out;

    zero_kernel<<<512, 256>>>(out);
    router_kernel<<<T, 128>>>(x, gate_w);
    gateup_kernel<<<dim3(M / 128, T / 64, E), 256>>>(x, w_gate, w_up);
    down_kernel<<<dim3(H / 128, T / 64, E), 256>>>(w_down, out);
}

// round 3
// speedup vs baseline: 1.4484x; 1.4484x over previous
#include <cuda_runtime.h>
#include <math.h>
#include <stdint.h>

#define T 2048
#define H 1024
#define M 512
#define E 32
#define TOPK 4
#define NROWS (T * TOPK)
#define PROWS (NROWS + 128)

// ------------------------- static device scratch ---------------------------
__device__ int   g_count[E];
__device__ int   g_off[E];
__device__ int   g_tok[E * T];
__device__ float g_wt[E * T];
__device__ int   g_psaid[NROWS];
__device__ float g_pwt[NROWS];
__device__ float X_g[(size_t)PROWS * H];
__device__ float g_hbuf[(size_t)PROWS * M];
__device__ float g_part[(size_t)NROWS * H];

// ------------------------- helpers -----------------------------------------
__device__ __forceinline__ uint32_t ftu(float f) {   // fp32 -> tf32 (round-to-nearest)
    uint32_t u; asm("cvt.rna.tf32.f32 %0, %1;" : "=r"(u) : "f"(f)); return u;
}
__device__ __forceinline__ uint4 cvt4(float4 v) {
    uint4 o; o.x = ftu(v.x); o.y = ftu(v.y); o.z = ftu(v.z); o.w = ftu(v.w); return o;
}
__device__ __forceinline__ void mma_tf32(float* c, const uint32_t* a, uint32_t b0, uint32_t b1) {
    asm volatile("mma.sync.aligned.m16n8k8.row.col.f32.tf32.tf32.f32 "
        "{%0,%1,%2,%3}, {%4,%5,%6,%7}, {%8,%9}, {%0,%1,%2,%3};"
        : "+f"(c[0]), "+f"(c[1]), "+f"(c[2]), "+f"(c[3])
        : "r"(a[0]), "r"(a[1]), "r"(a[2]), "r"(a[3]), "r"(b0), "r"(b1));
}

// ------------------------- small kernels -----------------------------------
__global__ void zero_counts() { if (threadIdx.x < E) g_count[threadIdx.x] = 0; }

__global__ void router_kernel(const float* __restrict__ x,
                              const float* __restrict__ gate_w) {
    __shared__ float xs[H];
    __shared__ float logits[E];
    int t = blockIdx.x;
    const float* xr = x + (size_t)t * H;
    for (int i = threadIdx.x; i < H; i += blockDim.x) xs[i] = xr[i];
    __syncthreads();
    int warp = threadIdx.x >> 5, lane = threadIdx.x & 31;
    for (int e = warp; e < E; e += 4) {
        const float* w = gate_w + (size_t)e * H;
        float s = 0.f;
        for (int i = lane; i < H; i += 32) s += xs[i] * w[i];
        #pragma unroll
        for (int o = 16; o > 0; o >>= 1) s += __shfl_xor_sync(0xffffffffu, s, o);
        if (lane == 0) logits[e] = s;
    }
    __syncthreads();
    if (threadIdx.x == 0) {
        int ids[TOPK]; float vals[TOPK];
        unsigned used = 0;
        for (int k = 0; k < TOPK; k++) {
            float best = -INFINITY; int bi = 0;
            for (int e = 0; e < E; e++)
                if (!((used >> e) & 1u) && logits[e] > best) { best = logits[e]; bi = e; }
            used |= (1u << bi); ids[k] = bi; vals[k] = best;
        }
        float mx = vals[0], se = 0.f, w4[TOPK];
        for (int k = 0; k < TOPK; k++) { w4[k] = expf(vals[k] - mx); se += w4[k]; }
        float inv = 1.0f / se;
        for (int k = 0; k < TOPK; k++) {
            int e = ids[k];
            int pos = atomicAdd(&g_count[e], 1);
            g_tok[e * T + pos] = t * TOPK + k;
            g_wt[e * T + pos] = w4[k] * inv;
        }
    }
}

__global__ void scan_kernel() {
    int lane = threadIdx.x;
    int c = g_count[lane];
    int ex = c;
    #pragma unroll
    for (int o = 1; o < 32; o <<= 1) {
        int v = __shfl_up_sync(0xffffffffu, ex, o);
        if (lane >= o) ex += v;
    }
    g_off[lane] = ex - c;
}

__global__ void gather_kernel(const float* __restrict__ x) {
    int e = blockIdx.x;
    int slot = blockIdx.y * 8 + (threadIdx.x >> 5);
    int lane = threadIdx.x & 31;
    if (slot >= g_count[e]) return;
    int aid = g_tok[e * T + slot];
    int row = g_off[e] + slot;
    if (lane == 0) { g_psaid[row] = aid; g_pwt[row] = g_wt[e * T + slot]; }
    const float4* src = (const float4*)(x + (size_t)(aid >> 2) * H);
    float4* dst = (float4*)(X_g + (size_t)row * H);
    #pragma unroll
    for (int i = 0; i < 8; i++) dst[lane + i * 32] = src[lane + i * 32];
}

// ------------------------- gate/up mma GEMM --------------------------------
// block: 128 packed rows x 128 m-cols; warps 2x4, warp tile 64x32, K chunks of 16
#define GU_STRIDE 20                    // uints per smem row (k=16 + pad)
#define GU_TILE  (128 * GU_STRIDE)      // 2560 uints
#define GU_SMEMB (2 * 3 * GU_TILE * 4)  // 61440 bytes

__global__ void __launch_bounds__(256, 1)
gateup_mma(const float* __restrict__ wg, const float* __restrict__ wu) {
    int e = blockIdx.z;
    int n = g_count[e];
    int t0 = blockIdx.y * 128;
    if (t0 >= n) return;
    int m0 = blockIdx.x * 128;

    extern __shared__ uint32_t sm[];
    __shared__ float swt[128];
    __shared__ int   said[128];

    int tid = threadIdx.x, lane = tid & 31, wid = tid >> 5;
    int gid = lane >> 2, tig = lane & 3;
    int wm = wid & 1, wn = wid >> 1;
    int base = g_off[e] + t0;

    if (tid < 128) {
        bool v = (t0 + tid) < n;
        said[tid] = v ? g_psaid[base + tid] : -1;
        swt[tid]  = v ? g_pwt[base + tid] : 0.f;
    }

    const float* xb  = X_g + (size_t)base * H;
    const float* wgb = wg + ((size_t)e * M + m0) * H;
    const float* wub = wu + ((size_t)e * M + m0) * H;

    float accG[4][4][4], accU[4][4][4];
    #pragma unroll
    for (int i = 0; i < 4; i++)
        #pragma unroll
        for (int j = 0; j < 4; j++)
            #pragma unroll
            for (int q = 0; q < 4; q++) { accG[i][j][q] = 0.f; accU[i][j][q] = 0.f; }

    uint4 pa[2], pg[2], pu[2];
    int rr0 = tid >> 2, jj4 = (tid & 3) * 4;       // i=0 mapping
    int rr1 = (tid + 256) >> 2;                    // i=1 mapping (same jj4)

    auto ldc = [&](int c) {
        int ko = c * 16;
        pa[0] = cvt4(*(const float4*)(xb  + (size_t)rr0 * H + ko + jj4));
        pg[0] = cvt4(*(const float4*)(wgb + (size_t)rr0 * H + ko + jj4));
        pu[0] = cvt4(*(const float4*)(wub + (size_t)rr0 * H + ko + jj4));
        pa[1] = cvt4(*(const float4*)(xb  + (size_t)rr1 * H + ko + jj4));
        pg[1] = cvt4(*(const float4*)(wgb + (size_t)rr1 * H + ko + jj4));
        pu[1] = cvt4(*(const float4*)(wub + (size_t)rr1 * H + ko + jj4));
    };
    auto sts = [&](int s) {
        uint32_t* A = sm + s * 3 * GU_TILE;
        uint32_t* G = A + GU_TILE;
        uint32_t* U = G + GU_TILE;
        *(uint4*)(A + rr0 * GU_STRIDE + jj4) = pa[0];
        *(uint4*)(G + rr0 * GU_STRIDE + jj4) = pg[0];
        *(uint4*)(U + rr0 * GU_STRIDE + jj4) = pu[0];
        *(uint4*)(A + rr1 * GU_STRIDE + jj4) = pa[1];
        *(uint4*)(G + rr1 * GU_STRIDE + jj4) = pg[1];
        *(uint4*)(U + rr1 * GU_STRIDE + jj4) = pu[1];
    };
    auto compute = [&](int s) {
        const uint32_t* A = sm + s * 3 * GU_TILE;
        const uint32_t* G = A + GU_TILE;
        const uint32_t* U = G + GU_TILE;
        #pragma unroll
        for (int k8 = 0; k8 < 2; k8++) {
            int k0 = k8 * 8;
            uint32_t a[4][4];
            #pragma unroll
            for (int mt = 0; mt < 4; mt++) {
                int r0 = wm * 64 + mt * 16 + gid;
                a[mt][0] = A[r0 * GU_STRIDE + k0 + tig];
                a[mt][1] = A[(r0 + 8) * GU_STRIDE + k0 + tig];
                a[mt][2] = A[r0 * GU_STRIDE + k0 + tig + 4];
                a[mt][3] = A[(r0 + 8) * GU_STRIDE + k0 + tig + 4];
            }
            #pragma unroll
            for (int nt = 0; nt < 4; nt++) {
                int nb = wn * 32 + nt * 8 + gid;
                uint32_t bg0 = G[nb * GU_STRIDE + k0 + tig];
                uint32_t bg1 = G[nb * GU_STRIDE + k0 + tig + 4];
                uint32_t bu0 = U[nb * GU_STRIDE + k0 + tig];
                uint32_t bu1 = U[nb * GU_STRIDE + k0 + tig + 4];
                #pragma unroll
                for (int mt = 0; mt < 4; mt++) {
                    mma_tf32(accG[mt][nt], a[mt], bg0, bg1);
                    mma_tf32(accU[mt][nt], a[mt], bu0, bu1);
                }
            }
        }
    };

    const int NC = H / 16;    // 64
    ldc(0); sts(0);
    __syncthreads();
    for (int c = 0; c < NC; c++) {
        int s = c & 1;
        if (c + 1 < NC) ldc(c + 1);
        compute(s);
        __syncthreads();
        if (c + 1 < NC) { sts(s ^ 1); __syncthreads(); }
    }

    // epilogue: h = silu(gate)*up*route_w
    #pragma unroll
    for (int mt = 0; mt < 4; mt++) {
        #pragma unroll
        for (int rh = 0; rh < 2; rh++) {
            int r = wm * 64 + mt * 16 + gid + rh * 8;
            int aid = said[r];
            if (aid < 0) continue;
            float wv = swt[r];
            float* hp = g_hbuf + (size_t)(base + r) * M + m0 + wn * 32;
            #pragma unroll
            for (int nt = 0; nt < 4; nt++) {
                float g0 = accG[mt][nt][rh * 2 + 0];
                float g1 = accG[mt][nt][rh * 2 + 1];
                float u0 = accU[mt][nt][rh * 2 + 0];
                float u1 = accU[mt][nt][rh * 2 + 1];
                float2 o;
                o.x = (g0 / (1.f + __expf(-g0))) * u0 * wv;
                o.y = (g1 / (1.f + __expf(-g1))) * u1 * wv;
                *(float2*)(hp + nt * 8 + tig * 2) = o;
            }
        }
    }
}

// ------------------------- down mma GEMM -----------------------------------
// block: 128 rows x 128 h-cols; warps 2x4, warp tile 64x32, K chunks of 32
#define DN_STRIDE 36
#define DN_TILE  (128 * DN_STRIDE)      // 4608 uints
#define DN_SMEMB (2 * 2 * DN_TILE * 4)  // 73728 bytes

__global__ void __launch_bounds__(256, 1)
down_mma(const float* __restrict__ wd) {
    int e = blockIdx.z;
    int n = g_count[e];
    int t0 = blockIdx.y * 128;
    if (t0 >= n) return;
    int h0 = blockIdx.x * 128;

    extern __shared__ uint32_t sm[];
    __shared__ int said[128];

    int tid = threadIdx.x, lane = tid & 31, wid = tid >> 5;
    int gid = lane >> 2, tig = lane & 3;
    int wm = wid & 1, wn = wid >> 1;
    int base = g_off[e] + t0;

    if (tid < 128) said[tid] = ((t0 + tid) < n) ? g_psaid[base + tid] : -1;

    const float* ab  = g_hbuf + (size_t)base * M;
    const float* wdb = wd + ((size_t)e * H + h0) * M;

    float acc[4][4][4];
    #pragma unroll
    for (int i = 0; i < 4; i++)
        #pragma unroll
        for (int j = 0; j < 4; j++)
            #pragma unroll
            for (int q = 0; q < 4; q++) acc[i][j][q] = 0.f;

    uint4 pa[4], pw[4];
    int rr[4], jj4 = (tid & 7) * 4;
    #pragma unroll
    for (int i = 0; i < 4; i++) rr[i] = (tid + i * 256) >> 3;

    auto ldc = [&](int c) {
        int ko = c * 32;
        #pragma unroll
        for (int i = 0; i < 4; i++) {
            pa[i] = cvt4(*(const float4*)(ab  + (size_t)rr[i] * M + ko + jj4));
            pw[i] = cvt4(*(const float4*)(wdb + (size_t)rr[i] * M + ko + jj4));
        }
    };
    auto sts = [&](int s) {
        uint32_t* A = sm + s * 2 * DN_TILE;
        uint32_t* W = A + DN_TILE;
        #pragma unroll
        for (int i = 0; i < 4; i++) {
            *(uint4*)(A + rr[i] * DN_STRIDE + jj4) = pa[i];
            *(uint4*)(W + rr[i] * DN_STRIDE + jj4) = pw[i];
        }
    };
    auto compute = [&](int s) {
        const uint32_t* A = sm + s * 2 * DN_TILE;
        const uint32_t* W = A + DN_TILE;
        #pragma unroll
        for (int k8 = 0; k8 < 4; k8++) {
            int k0 = k8 * 8;
            uint32_t a[4][4];
            #pragma unroll
            for (int mt = 0; mt < 4; mt++) {
                int r0 = wm * 64 + mt * 16 + gid;
                a[mt][0] = A[r0 * DN_STRIDE + k0 + tig];
                a[mt][1] = A[(r0 + 8) * DN_STRIDE + k0 + tig];
                a[mt][2] = A[r0 * DN_STRIDE + k0 + tig + 4];
                a[mt][3] = A[(r0 + 8) * DN_STRIDE + k0 + tig + 4];
            }
            #pragma unroll
            for (int nt = 0; nt < 4; nt++) {
                int nb = wn * 32 + nt * 8 + gid;
                uint32_t b0 = W[nb * DN_STRIDE + k0 + tig];
                uint32_t b1 = W[nb * DN_STRIDE + k0 + tig + 4];
                #pragma unroll
                for (int mt = 0; mt < 4; mt++)
                    mma_tf32(acc[mt][nt], a[mt], b0, b1);
            }
        }
    };

    const int NC = M / 32;    // 16
    ldc(0); sts(0);
    __syncthreads();
    for (int c = 0; c < NC; c++) {
        int s = c & 1;
        if (c + 1 < NC) ldc(c + 1);
        compute(s);
        __syncthreads();
        if (c + 1 < NC) { sts(s ^ 1); __syncthreads(); }
    }

    #pragma unroll
    for (int mt = 0; mt < 4; mt++) {
        #pragma unroll
        for (int rh = 0; rh < 2; rh++) {
            int r = wm * 64 + mt * 16 + gid + rh * 8;
            int aid = said[r];
            if (aid < 0) continue;
            float* op = g_part + (size_t)aid * H + h0 + wn * 32;
            #pragma unroll
            for (int nt = 0; nt < 4; nt++) {
                float2 o;
                o.x = acc[mt][nt][rh * 2 + 0];
                o.y = acc[mt][nt][rh * 2 + 1];
                *(float2*)(op + nt * 8 + tig * 2) = o;
            }
        }
    }
}

// ------------------------- final reduce ------------------------------------
__global__ void reduce_kernel(float* __restrict__ out) {
    int i = blockIdx.x * 256 + threadIdx.x;
    int t = i >> 8;
    int h4 = i & 255;
    const float4* p = (const float4*)(g_part + (size_t)t * 4 * H) + h4;
    float4 a = p[0], b = p[256], c = p[512], d = p[768];
    float4 o;
    o.x = a.x + b.x + c.x + d.x;
    o.y = a.y + b.y + c.y + d.y;
    o.z = a.z + b.z + c.z + d.z;
    o.w = a.w + b.w + c.w + d.w;
    ((float4*)out)[i] = o;
}

// ------------------------- launcher ----------------------------------------
extern "C" void kernel_launch(void* const* d_in, const int* in_sizes, int n_in,
                              void* d_out, int out_size) {
    const float* x      = (const float*)d_in[0];
    const float* gate_w = (const float*)d_in[1];
    const float* w_gate = (const float*)d_in[2];
    const float* w_up   = (const float*)d_in[3];
    const float* w_down = (const float*)d_in[4];
    float* out = (float*)d_out;

    cudaFuncSetAttribute(gateup_mma, cudaFuncAttributeMaxDynamicSharedMemorySize, GU_SMEMB);
    cudaFuncSetAttribute(down_mma,   cudaFuncAttributeMaxDynamicSharedMemorySize, DN_SMEMB);

    zero_counts<<<1, 32>>>();
    router_kernel<<<T, 128>>>(x, gate_w);
    scan_kernel<<<1, 32>>>();
    gather_kernel<<<dim3(E, T / 8), 256>>>(x);
    gateup_mma<<<dim3(M / 128, 16, E), 256, GU_SMEMB>>>(w_gate, w_up);
    down_mma<<<dim3(H / 128, 16, E), 256, DN_SMEMB>>>(w_down);
    reduce_kernel<<<T * H / 4 / 256, 256>>>(out);
}

// round 4
// speedup vs baseline: 1.9271x; 1.3305x over previous
#include <cuda_runtime.h>
#include <math.h>
#include <stdint.h>

#define T 2048
#define H 1024
#define M 512
#define E 32
#define TOPK 4
#define NROWS (T * TOPK)
#define PROWS (NROWS + 128)

// ------------------------- static device scratch ---------------------------
__device__ int   g_count[E];
__device__ int   g_off[E];          // exclusive prefix of counts (packed row base)
__device__ int   g_typre[E + 1];    // exclusive prefix of ceil(count/128); [E]=total
__device__ int   g_tok[E * T];      // per-expert slot -> aid (t*4+k)
__device__ float g_wt[E * T];
__device__ float g_hbuf[(size_t)PROWS * M];
__device__ float g_part[(size_t)NROWS * H];

// ------------------------- helpers -----------------------------------------
__device__ __forceinline__ uint32_t ftu(float f) {
    uint32_t u; asm("cvt.rna.tf32.f32 %0, %1;" : "=r"(u) : "f"(f)); return u;
}
__device__ __forceinline__ uint4 cvt4(float4 v) {
    uint4 o; o.x = ftu(v.x); o.y = ftu(v.y); o.z = ftu(v.z); o.w = ftu(v.w); return o;
}
__device__ __forceinline__ void mma_tf32(float* c, const uint32_t* a, uint32_t b0, uint32_t b1) {
    asm volatile("mma.sync.aligned.m16n8k8.row.col.f32.tf32.tf32.f32 "
        "{%0,%1,%2,%3}, {%4,%5,%6,%7}, {%8,%9}, {%0,%1,%2,%3};"
        : "+f"(c[0]), "+f"(c[1]), "+f"(c[2]), "+f"(c[3])
        : "r"(a[0]), "r"(a[1]), "r"(a[2]), "r"(a[3]), "r"(b0), "r"(b1));
}

// ------------------------- small kernels -----------------------------------
__global__ void zero_counts() { if (threadIdx.x < E) g_count[threadIdx.x] = 0; }

__global__ void router_kernel(const float* __restrict__ x,
                              const float* __restrict__ gate_w) {
    __shared__ float xs[H];
    __shared__ float logits[E];
    int t = blockIdx.x;
    const float* xr = x + (size_t)t * H;
    for (int i = threadIdx.x; i < H; i += blockDim.x) xs[i] = xr[i];
    __syncthreads();
    int warp = threadIdx.x >> 5, lane = threadIdx.x & 31;
    for (int e = warp; e < E; e += 4) {
        const float* w = gate_w + (size_t)e * H;
        float s = 0.f;
        for (int i = lane; i < H; i += 32) s += xs[i] * w[i];
        #pragma unroll
        for (int o = 16; o > 0; o >>= 1) s += __shfl_xor_sync(0xffffffffu, s, o);
        if (lane == 0) logits[e] = s;
    }
    __syncthreads();
    if (threadIdx.x == 0) {
        int ids[TOPK]; float vals[TOPK];
        unsigned used = 0;
        for (int k = 0; k < TOPK; k++) {
            float best = -INFINITY; int bi = 0;
            for (int e = 0; e < E; e++)
                if (!((used >> e) & 1u) && logits[e] > best) { best = logits[e]; bi = e; }
            used |= (1u << bi); ids[k] = bi; vals[k] = best;
        }
        float mx = vals[0], se = 0.f, w4[TOPK];
        for (int k = 0; k < TOPK; k++) { w4[k] = expf(vals[k] - mx); se += w4[k]; }
        float inv = 1.0f / se;
        for (int k = 0; k < TOPK; k++) {
            int e = ids[k];
            int pos = atomicAdd(&g_count[e], 1);
            g_tok[e * T + pos] = t * TOPK + k;
            g_wt[e * T + pos] = w4[k] * inv;
        }
    }
}

__global__ void scan_kernel() {
    int lane = threadIdx.x;
    int c = g_count[lane];
    int ex = c;
    #pragma unroll
    for (int o = 1; o < 32; o <<= 1) {
        int v = __shfl_up_sync(0xffffffffu, ex, o);
        if (lane >= o) ex += v;
    }
    g_off[lane] = ex - c;
    int ty = (c + 127) >> 7;
    int tp = ty;
    #pragma unroll
    for (int o = 1; o < 32; o <<= 1) {
        int v = __shfl_up_sync(0xffffffffu, tp, o);
        if (lane >= o) tp += v;
    }
    g_typre[lane] = tp - ty;
    if (lane == 31) g_typre[E] = tp;
}

// ------------------------- gate/up mma GEMM --------------------------------
// persistent; 512 threads, 16 warps in 4x4 grid; block tile 128x128; warp 32x32
// K chunks of 32; smem stride 36 (conflict-free)
#define GU_STRIDE 36
#define GU_TILEW (128 * GU_STRIDE)         // 4608 words per array
#define GU_SMEMB (2 * 3 * GU_TILEW * 4)    // 110592 bytes

__global__ void __launch_bounds__(512, 1)
gateup_mma(const float* __restrict__ x,
           const float* __restrict__ wg, const float* __restrict__ wu) {
    extern __shared__ uint32_t sm[];
    __shared__ int   styp[E + 1];
    __shared__ int   said_s[128];
    __shared__ float swt_s[128];

    int tid = threadIdx.x, lane = tid & 31, wid = tid >> 5;
    int gid = lane >> 2, tig = lane & 3;
    int wm = wid & 3, wn = wid >> 2;

    if (tid <= E) styp[tid] = g_typre[tid];
    __syncthreads();
    int totalW = styp[E] * 4;

    int rr0 = tid >> 3;                 // loader row for slot i=0
    int rr1 = (tid + 512) >> 3;         // i=1
    int jj4 = (tid & 7) * 4;

    for (int w = blockIdx.x; w < totalW; w += gridDim.x) {
        int ytl = w >> 2, xt = w & 3;
        int e = 0;
        while (styp[e + 1] <= ytl) e++;
        int t0 = (ytl - styp[e]) * 128;
        int m0 = xt * 128;
        int n  = g_count[e];
        int gbase = g_off[e] + t0;

        __syncthreads();   // smem reuse guard from previous tile
        if (tid < 128) {
            int slot = t0 + tid;
            bool v = slot < n;
            said_s[tid] = v ? g_tok[e * T + slot] : -1;
            swt_s[tid]  = v ? g_wt[e * T + slot] : 0.f;
        }
        __syncthreads();

        const float* wgb = wg + ((size_t)e * M + m0) * H;
        const float* wub = wu + ((size_t)e * M + m0) * H;

        float accG[2][4][4], accU[2][4][4];
        #pragma unroll
        for (int i = 0; i < 2; i++)
            #pragma unroll
            for (int j = 0; j < 4; j++)
                #pragma unroll
                for (int q = 0; q < 4; q++) { accG[i][j][q] = 0.f; accU[i][j][q] = 0.f; }

        uint4 pa[2], pg[2], pu[2];
        int aid0 = said_s[rr0], aid1 = said_s[rr1];

        auto ldc = [&](int c) {
            int ko = c * 32;
            pa[0] = (aid0 >= 0) ? cvt4(*(const float4*)(x + (size_t)(aid0 >> 2) * H + ko + jj4))
                                : make_uint4(0, 0, 0, 0);
            pa[1] = (aid1 >= 0) ? cvt4(*(const float4*)(x + (size_t)(aid1 >> 2) * H + ko + jj4))
                                : make_uint4(0, 0, 0, 0);
            pg[0] = cvt4(*(const float4*)(wgb + (size_t)rr0 * H + ko + jj4));
            pg[1] = cvt4(*(const float4*)(wgb + (size_t)rr1 * H + ko + jj4));
            pu[0] = cvt4(*(const float4*)(wub + (size_t)rr0 * H + ko + jj4));
            pu[1] = cvt4(*(const float4*)(wub + (size_t)rr1 * H + ko + jj4));
        };
        auto sts = [&](int s) {
            uint32_t* A = sm + s * 3 * GU_TILEW;
            uint32_t* G = A + GU_TILEW;
            uint32_t* U = G + GU_TILEW;
            *(uint4*)(A + rr0 * GU_STRIDE + jj4) = pa[0];
            *(uint4*)(A + rr1 * GU_STRIDE + jj4) = pa[1];
            *(uint4*)(G + rr0 * GU_STRIDE + jj4) = pg[0];
            *(uint4*)(G + rr1 * GU_STRIDE + jj4) = pg[1];
            *(uint4*)(U + rr0 * GU_STRIDE + jj4) = pu[0];
            *(uint4*)(U + rr1 * GU_STRIDE + jj4) = pu[1];
        };
        auto compute = [&](int s) {
            const uint32_t* A = sm + s * 3 * GU_TILEW;
            const uint32_t* G = A + GU_TILEW;
            const uint32_t* U = G + GU_TILEW;
            #pragma unroll
            for (int k8 = 0; k8 < 4; k8++) {
                int k0 = k8 * 8;
                uint32_t a[2][4];
                #pragma unroll
                for (int mt = 0; mt < 2; mt++) {
                    int r0 = wm * 32 + mt * 16 + gid;
                    a[mt][0] = A[r0 * GU_STRIDE + k0 + tig];
                    a[mt][1] = A[(r0 + 8) * GU_STRIDE + k0 + tig];
                    a[mt][2] = A[r0 * GU_STRIDE + k0 + tig + 4];
                    a[mt][3] = A[(r0 + 8) * GU_STRIDE + k0 + tig + 4];
                }
                #pragma unroll
                for (int nt = 0; nt < 4; nt++) {
                    int nb = wn * 32 + nt * 8 + gid;
                    uint32_t bg0 = G[nb * GU_STRIDE + k0 + tig];
                    uint32_t bg1 = G[nb * GU_STRIDE + k0 + tig + 4];
                    uint32_t bu0 = U[nb * GU_STRIDE + k0 + tig];
                    uint32_t bu1 = U[nb * GU_STRIDE + k0 + tig + 4];
                    #pragma unroll
                    for (int mt = 0; mt < 2; mt++) {
                        mma_tf32(accG[mt][nt], a[mt], bg0, bg1);
                        mma_tf32(accU[mt][nt], a[mt], bu0, bu1);
                    }
                }
            }
        };

        const int NC = H / 32;   // 32
        ldc(0); sts(0);
        __syncthreads();
        for (int c = 0; c < NC; c++) {
            int s = c & 1;
            if (c + 1 < NC) ldc(c + 1);
            compute(s);
            __syncthreads();
            if (c + 1 < NC) { sts(s ^ 1); __syncthreads(); }
        }

        // epilogue: h = silu(gate)*up*route_w
        #pragma unroll
        for (int mt = 0; mt < 2; mt++) {
            #pragma unroll
            for (int rh = 0; rh < 2; rh++) {
                int r = wm * 32 + mt * 16 + gid + rh * 8;
                int aid = said_s[r];
                if (aid < 0) continue;
                float wv = swt_s[r];
                float* hp = g_hbuf + (size_t)(gbase + r) * M + m0 + wn * 32;
                #pragma unroll
                for (int nt = 0; nt < 4; nt++) {
                    float g0 = accG[mt][nt][rh * 2 + 0];
                    float g1 = accG[mt][nt][rh * 2 + 1];
                    float u0 = accU[mt][nt][rh * 2 + 0];
                    float u1 = accU[mt][nt][rh * 2 + 1];
                    float2 o;
                    o.x = (g0 / (1.f + __expf(-g0))) * u0 * wv;
                    o.y = (g1 / (1.f + __expf(-g1))) * u1 * wv;
                    *(float2*)(hp + nt * 8 + tig * 2) = o;
                }
            }
        }
    }
}

// ------------------------- down mma GEMM -----------------------------------
// persistent; 256 threads, 8 warps in 2x4; block 128x128; warp 64x32; K chunk 32
#define DN_STRIDE 36
#define DN_TILEW (128 * DN_STRIDE)         // 4608 words
#define DN_SMEMB (2 * 2 * DN_TILEW * 4)    // 73728 bytes

__global__ void __launch_bounds__(256, 2)
down_mma(const float* __restrict__ wd) {
    extern __shared__ uint32_t sm[];
    __shared__ int styp[E + 1];
    __shared__ int said_s[128];

    int tid = threadIdx.x, lane = tid & 31, wid = tid >> 5;
    int gid = lane >> 2, tig = lane & 3;
    int wm = wid & 1, wn = wid >> 1;

    if (tid <= E) styp[tid] = g_typre[tid];
    __syncthreads();
    int totalW = styp[E] * 8;

    int rr[4], jj4 = (tid & 7) * 4;
    #pragma unroll
    for (int i = 0; i < 4; i++) rr[i] = (tid + i * 256) >> 3;

    for (int w = blockIdx.x; w < totalW; w += gridDim.x) {
        int ytl = w >> 3, xt = w & 7;
        int e = 0;
        while (styp[e + 1] <= ytl) e++;
        int t0 = (ytl - styp[e]) * 128;
        int h0 = xt * 128;
        int n  = g_count[e];
        int gbase = g_off[e] + t0;

        __syncthreads();
        if (tid < 128) {
            int slot = t0 + tid;
            said_s[tid] = (slot < n) ? g_tok[e * T + slot] : -1;
        }
        __syncthreads();

        const float* ab  = g_hbuf + (size_t)gbase * M;
        const float* wdb = wd + ((size_t)e * H + h0) * M;

        float acc[4][4][4];
        #pragma unroll
        for (int i = 0; i < 4; i++)
            #pragma unroll
            for (int j = 0; j < 4; j++)
                #pragma unroll
                for (int q = 0; q < 4; q++) acc[i][j][q] = 0.f;

        uint4 pa[4], pw[4];
        auto ldc = [&](int c) {
            int ko = c * 32;
            #pragma unroll
            for (int i = 0; i < 4; i++) {
                pa[i] = cvt4(*(const float4*)(ab  + (size_t)rr[i] * M + ko + jj4));
                pw[i] = cvt4(*(const float4*)(wdb + (size_t)rr[i] * M + ko + jj4));
            }
        };
        auto sts = [&](int s) {
            uint32_t* A = sm + s * 2 * DN_TILEW;
            uint32_t* W = A + DN_TILEW;
            #pragma unroll
            for (int i = 0; i < 4; i++) {
                *(uint4*)(A + rr[i] * DN_STRIDE + jj4) = pa[i];
                *(uint4*)(W + rr[i] * DN_STRIDE + jj4) = pw[i];
            }
        };
        auto compute = [&](int s) {
            const uint32_t* A = sm + s * 2 * DN_TILEW;
            const uint32_t* W = A + DN_TILEW;
            #pragma unroll
            for (int k8 = 0; k8 < 4; k8++) {
                int k0 = k8 * 8;
                uint32_t a[4][4];
                #pragma unroll
                for (int mt = 0; mt < 4; mt++) {
                    int r0 = wm * 64 + mt * 16 + gid;
                    a[mt][0] = A[r0 * DN_STRIDE + k0 + tig];
                    a[mt][1] = A[(r0 + 8) * DN_STRIDE + k0 + tig];
                    a[mt][2] = A[r0 * DN_STRIDE + k0 + tig + 4];
                    a[mt][3] = A[(r0 + 8) * DN_STRIDE + k0 + tig + 4];
                }
                #pragma unroll
                for (int nt = 0; nt < 4; nt++) {
                    int nb = wn * 32 + nt * 8 + gid;
                    uint32_t b0 = W[nb * DN_STRIDE + k0 + tig];
                    uint32_t b1 = W[nb * DN_STRIDE + k0 + tig + 4];
                    #pragma unroll
                    for (int mt = 0; mt < 4; mt++)
                        mma_tf32(acc[mt][nt], a[mt], b0, b1);
                }
            }
        };

        const int NC = M / 32;   // 16
        ldc(0); sts(0);
        __syncthreads();
        for (int c = 0; c < NC; c++) {
            int s = c & 1;
            if (c + 1 < NC) ldc(c + 1);
            compute(s);
            __syncthreads();
            if (c + 1 < NC) { sts(s ^ 1); __syncthreads(); }
        }

        #pragma unroll
        for (int mt = 0; mt < 4; mt++) {
            #pragma unroll
            for (int rh = 0; rh < 2; rh++) {
                int r = wm * 64 + mt * 16 + gid + rh * 8;
                int aid = said_s[r];
                if (aid < 0) continue;
                float* op = g_part + (size_t)aid * H + h0 + wn * 32;
                #pragma unroll
                for (int nt = 0; nt < 4; nt++) {
                    float2 o;
                    o.x = acc[mt][nt][rh * 2 + 0];
                    o.y = acc[mt][nt][rh * 2 + 1];
                    *(float2*)(op + nt * 8 + tig * 2) = o;
                }
            }
        }
    }
}

// ------------------------- final reduce ------------------------------------
__global__ void reduce_kernel(float* __restrict__ out) {
    int i = blockIdx.x * 256 + threadIdx.x;
    int t = i >> 8;
    int h4 = i & 255;
    const float4* p = (const float4*)(g_part + (size_t)t * 4 * H) + h4;
    float4 a = p[0], b = p[256], c = p[512], d = p[768];
    float4 o;
    o.x = a.x + b.x + c.x + d.x;
    o.y = a.y + b.y + c.y + d.y;
    o.z = a.z + b.z + c.z + d.z;
    o.w = a.w + b.w + c.w + d.w;
    ((float4*)out)[i] = o;
}

// ------------------------- launcher ----------------------------------------
extern "C" void kernel_launch(void* const* d_in, const int* in_sizes, int n_in,
                              void* d_out, int out_size) {
    const float* x      = (const float*)d_in[0];
    const float* gate_w = (const float*)d_in[1];
    const float* w_gate = (const float*)d_in[2];
    const float* w_up   = (const float*)d_in[3];
    const float* w_down = (const float*)d_in[4];
    float* out = (float*)d_out;

    cudaFuncSetAttribute(gateup_mma, cudaFuncAttributeMaxDynamicSharedMemorySize, GU_SMEMB);
    cudaFuncSetAttribute(down_mma,   cudaFuncAttributeMaxDynamicSharedMemorySize, DN_SMEMB);

    zero_counts<<<1, 32>>>();
    router_kernel<<<T, 128>>>(x, gate_w);
    scan_kernel<<<1, 32>>>();
    gateup_mma<<<148, 512, GU_SMEMB>>>(x, w_gate, w_up);
    down_mma<<<296, 256, DN_SMEMB>>>(w_down);
    reduce_kernel<<<T * H / 4 / 256, 256>>>(out);
}